// round 16
// baseline (speedup 1.0000x reference)
#include <cuda_runtime.h>
#include <cuda_bf16.h>
#include <math.h>
#include <stdint.h>

#define Bb 4
#define Ss 1024
#define Dd 1024
#define Hh 16
#define HD 64
#define BHt (Bb*Hh)
#define Mrows (Bb*Ss)

// ---------------- device scratch ----------------
__device__ __nv_bfloat16 g_qh[(size_t)Mrows*Dd];
__device__ __nv_bfloat16 g_ql[(size_t)Mrows*Dd];
__device__ __nv_bfloat16 g_kh[(size_t)Mrows*Dd];
__device__ __nv_bfloat16 g_kl[(size_t)Mrows*Dd];
__device__ __nv_bfloat16 g_vh[(size_t)Mrows*Dd];
__device__ __nv_bfloat16 g_vl[(size_t)Mrows*Dd];
__device__ __nv_bfloat16 g_wqh[(size_t)Dd*Dd];
__device__ __nv_bfloat16 g_wql[(size_t)Dd*Dd];
__device__ __nv_bfloat16 g_wkh[(size_t)Dd*Dd];
__device__ __nv_bfloat16 g_wkl[(size_t)Dd*Dd];
__device__ __nv_bfloat16 g_wvh[(size_t)Dd*Dd];
__device__ __nv_bfloat16 g_wvl[(size_t)Dd*Dd];
__device__ __nv_bfloat16 g_woh[(size_t)Dd*Dd];
__device__ __nv_bfloat16 g_wol[(size_t)Dd*Dd];
__device__ float g_x[(size_t)Mrows*Dd];
__device__ float g_rowsum[(size_t)BHt*Ss];
// P as bf16 hi/lo in MMA-fragment order (uint32 = bf16x2)
__device__ uint32_t g_pfh[(size_t)BHt*Ss*Ss/2];
__device__ uint32_t g_pfl[(size_t)BHt*Ss*Ss/2];
__device__ float g_p_fallback[(size_t)BHt*Ss*Ss];

// ---------------- helpers ----------------
__device__ __forceinline__ uint32_t smem_u32(const void* p) {
    uint32_t a;
    asm("{ .reg .u64 t; cvta.to.shared.u64 t, %1; cvt.u32.u64 %0, t; }" : "=r"(a) : "l"(p));
    return a;
}
__device__ __forceinline__ void ldsm_x4(uint32_t* r, uint32_t addr) {
    asm volatile("ldmatrix.sync.aligned.m8n8.x4.shared.b16 {%0,%1,%2,%3}, [%4];"
                 : "=r"(r[0]), "=r"(r[1]), "=r"(r[2]), "=r"(r[3]) : "r"(addr));
}
__device__ __forceinline__ void ldsm_x2t(uint32_t* r, uint32_t addr) {
    asm volatile("ldmatrix.sync.aligned.m8n8.x2.trans.shared.b16 {%0,%1}, [%2];"
                 : "=r"(r[0]), "=r"(r[1]) : "r"(addr));
}
__device__ __forceinline__ void mma16816(float* c, const uint32_t* a, const uint32_t* b) {
    asm volatile(
        "mma.sync.aligned.m16n8k16.row.col.f32.bf16.bf16.f32 "
        "{%0,%1,%2,%3}, {%4,%5,%6,%7}, {%8,%9}, {%0,%1,%2,%3};"
        : "+f"(c[0]), "+f"(c[1]), "+f"(c[2]), "+f"(c[3])
        : "r"(a[0]), "r"(a[1]), "r"(a[2]), "r"(a[3]), "r"(b[0]), "r"(b[1]));
}
__device__ __forceinline__ void split2(float x, float y, uint32_t& h, uint32_t& l) {
    __nv_bfloat16 hx = __float2bfloat16_rn(x);
    __nv_bfloat16 hy = __float2bfloat16_rn(y);
    __nv_bfloat162 hp; hp.x = hx; hp.y = hy;
    __nv_bfloat162 lp;
    lp.x = __float2bfloat16_rn(x - __bfloat162float(hx));
    lp.y = __float2bfloat16_rn(y - __bfloat162float(hy));
    h = *(uint32_t*)&hp;
    l = *(uint32_t*)&lp;
}
__device__ __forceinline__ void split8(const float4 a, const float4 b, uint4& h, uint4& l) {
    split2(a.x, a.y, h.x, l.x);
    split2(a.z, a.w, h.y, l.y);
    split2(b.x, b.y, h.z, l.z);
    split2(b.z, b.w, h.w, l.w);
}
__device__ __forceinline__ float2 bf2f2(uint32_t u) {
    __nv_bfloat162 t = *(__nv_bfloat162*)&u;
    return make_float2(__bfloat162float(t.x), __bfloat162float(t.y));
}

// ---------------- fp32 -> bf16 hi/lo split (weights, one-time) ----------------
__global__ __launch_bounds__(256) void split_w(
    const float* __restrict__ x, __nv_bfloat16* __restrict__ hi,
    __nv_bfloat16* __restrict__ lo)
{
    int i = blockIdx.x * blockDim.x + threadIdx.x;
    float4 v0 = ((const float4*)x)[2 * i];
    float4 v1 = ((const float4*)x)[2 * i + 1];
    uint4 h, l;
    split8(v0, v1, h, l);
    ((uint4*)hi)[i] = h;
    ((uint4*)lo)[i] = l;
}

// --------- round-12 128x128 GEMM: A fp32 (in-kernel split), W pre-split bf16 ---------
__global__ __launch_bounds__(256, 2) void gemm_aw_tc(
    const float* __restrict__ A,
    const __nv_bfloat16* __restrict__ Bh, const __nv_bfloat16* __restrict__ Bl,
    const float* __restrict__ bias,
    float* __restrict__ Cf, __nv_bfloat16* __restrict__ Ch,
    __nv_bfloat16* __restrict__ Cl, int mode,
    int Mn, int Nn, int Kn)
{
    __shared__ __align__(16) __nv_bfloat16 As[128][64];
    __shared__ __align__(16) __nv_bfloat16 Bs[2][32][128];

    const int tid = threadIdx.x;
    const int warp = tid >> 5, lane = tid & 31;
    const int wm = (warp >> 2) << 6;
    const int wn = (warp & 3) << 5;
    const int bm = blockIdx.y << 7, bn = blockIdx.x << 7;

    const uint32_t as0 = smem_u32(&As[0][0]);
    const uint32_t bs0 = smem_u32(&Bs[0][0][0]);

    float acc[4][4][4];
#pragma unroll
    for (int i = 0; i < 4; i++)
#pragma unroll
        for (int j = 0; j < 4; j++)
#pragma unroll
            for (int r = 0; r < 4; r++) acc[i][j][r] = 0.f;

    const int arow = tid >> 1, acol = (tid & 1) << 4;
    const float* gA = A + (size_t)(bm + arow) * Kn + acol;
    const int bk = tid >> 3, bcol = (tid & 7) << 4;
    const __nv_bfloat16* gBh = Bh + (size_t)bk * Nn + bn + bcol;
    const __nv_bfloat16* gBl = Bl + (size_t)bk * Nn + bn + bcol;

    char* apB = (char*)(&As[0][0]) + arow * 128;
    char* bpB = (char*)(&Bs[0][0][0]) + bk * 256;
    const int swa = arow & 7, swb = bk & 7;
    const int ac0 = (tid & 1) << 1;
    const int bc0 = (tid & 7) << 1;

    for (int k0 = 0; k0 < Kn; k0 += 32) {
        float4 fa0 = *(const float4*)(gA + k0);
        float4 fa1 = *(const float4*)(gA + k0 + 4);
        float4 fa2 = *(const float4*)(gA + k0 + 8);
        float4 fa3 = *(const float4*)(gA + k0 + 12);
        uint4 vbh0 = *(const uint4*)(gBh + (size_t)k0 * Nn);
        uint4 vbh1 = *(const uint4*)(gBh + (size_t)k0 * Nn + 8);
        uint4 vbl0 = *(const uint4*)(gBl + (size_t)k0 * Nn);
        uint4 vbl1 = *(const uint4*)(gBl + (size_t)k0 * Nn + 8);
        uint4 ah0, al0, ah1, al1;
        split8(fa0, fa1, ah0, al0);
        split8(fa2, fa3, ah1, al1);
        __syncthreads();
        *(uint4*)(apB + (((ac0 | 0) ^ swa) << 4)) = ah0;
        *(uint4*)(apB + (((ac0 | 1) ^ swa) << 4)) = ah1;
        *(uint4*)(apB + ((((ac0 | 0) + 4) ^ swa) << 4)) = al0;
        *(uint4*)(apB + ((((ac0 | 1) + 4) ^ swa) << 4)) = al1;
        *(uint4*)(bpB + (((bc0 | 0) ^ swb) << 4)) = vbh0;
        *(uint4*)(bpB + (((bc0 | 1) ^ swb) << 4)) = vbh1;
        *(uint4*)(bpB + 8192 + (((bc0 | 0) ^ swb) << 4)) = vbl0;
        *(uint4*)(bpB + 8192 + (((bc0 | 1) ^ swb) << 4)) = vbl1;
        __syncthreads();

#pragma unroll
        for (int ks = 0; ks < 2; ks++) {
            const int r15 = lane & 15;
            const int choff = (ks << 1) + (lane >> 4);
            uint32_t bf[2][4][2];
            const int krow = (ks << 4) + r15;
            const int swk = krow & 7;
#pragma unroll
            for (int nf = 0; nf < 4; nf++) {
                int chunk = (wn + (nf << 3)) >> 3;
                uint32_t ad = bs0 + krow * 256 + ((chunk ^ swk) << 4);
                ldsm_x2t(bf[0][nf], ad);
                ldsm_x2t(bf[1][nf], ad + 8192);
            }
            uint32_t af[4][4];
#pragma unroll
            for (int mf = 0; mf < 4; mf++) {
                int row = wm + (mf << 4) + r15;
                int sw = row & 7;
                ldsm_x4(af[mf], as0 + row * 128 + ((choff ^ sw) << 4));
            }
#pragma unroll
            for (int mf = 0; mf < 4; mf++)
#pragma unroll
                for (int nf = 0; nf < 4; nf++) {
                    mma16816(acc[mf][nf], af[mf], bf[0][nf]);
                    mma16816(acc[mf][nf], af[mf], bf[1][nf]);
                }
#pragma unroll
            for (int mf = 0; mf < 4; mf++) {
                int row = wm + (mf << 4) + r15;
                int sw = row & 7;
                ldsm_x4(af[mf], as0 + row * 128 + (((choff + 4) ^ sw) << 4));
            }
#pragma unroll
            for (int mf = 0; mf < 4; mf++)
#pragma unroll
                for (int nf = 0; nf < 4; nf++)
                    mma16816(acc[mf][nf], af[mf], bf[0][nf]);
        }
    }

    const int gr = lane >> 2, gc = (lane & 3) << 1;
#pragma unroll
    for (int mf = 0; mf < 4; mf++) {
        int r0 = bm + wm + (mf << 4) + gr;
#pragma unroll
        for (int nf = 0; nf < 4; nf++) {
            int col = bn + wn + (nf << 3) + gc;
            float2 bv = *(const float2*)(bias + col);
            float c00 = acc[mf][nf][0] + bv.x, c01 = acc[mf][nf][1] + bv.y;
            float c10 = acc[mf][nf][2] + bv.x, c11 = acc[mf][nf][3] + bv.y;
            if (mode == 0) {
                *(float2*)(Cf + (size_t)r0 * Nn + col) = make_float2(c00, c01);
                *(float2*)(Cf + (size_t)(r0 + 8) * Nn + col) = make_float2(c10, c11);
            } else {
                uint32_t h, l;
                split2(c00, c01, h, l);
                *(uint32_t*)(Ch + (size_t)r0 * Nn + col) = h;
                *(uint32_t*)(Cl + (size_t)r0 * Nn + col) = l;
                split2(c10, c11, h, l);
                *(uint32_t*)(Ch + (size_t)(r0 + 8) * Nn + col) = h;
                *(uint32_t*)(Cl + (size_t)(r0 + 8) * Nn + col) = l;
            }
        }
    }
}

// ---- energy: QK^T/8 + mask + exp -> fragment-order bf16 hi/lo P; rowsums ----
__global__ __launch_bounds__(256) void attn_energy_tc(
    const __nv_bfloat16* __restrict__ qh, const __nv_bfloat16* __restrict__ ql,
    const __nv_bfloat16* __restrict__ kh, const __nv_bfloat16* __restrict__ kl,
    const int* __restrict__ mask,
    uint32_t* __restrict__ Pfh, uint32_t* __restrict__ Pfl)
{
    __shared__ __align__(16) __nv_bfloat16 Qh[64][64], Ql[64][64];
    __shared__ __align__(16) __nv_bfloat16 Kh[64][64], Kl[64][64];
    __shared__ float red[64][4];

    const int tid = threadIdx.x;
    const int warp = tid >> 5, lane = tid & 31;
    const int wm = (warp >> 2) << 5;
    const int wn = (warp & 3) << 4;
    const int bh = blockIdx.y;
    const int b = bh >> 4, h = bh & 15;
    const int qt = blockIdx.x;
    const int q0 = qt << 6;

    const uint32_t qh0 = smem_u32(&Qh[0][0]);
    const uint32_t ql0 = smem_u32(&Ql[0][0]);
    const uint32_t kh0 = smem_u32(&Kh[0][0]);
    const uint32_t kl0 = smem_u32(&Kl[0][0]);

    const int gr = lane >> 2, gc = (lane & 3) << 1;

    uint32_t mb0 = 0, mb1 = 0;
#pragma unroll
    for (int kt = 0; kt < 16; kt++)
#pragma unroll
        for (int nf = 0; nf < 2; nf++) {
            int col = (kt << 6) + wn + (nf << 3) + gc;
            int bit = (kt << 1) | nf;
            if (mask[b * Ss + col]) mb0 |= (1u << bit);
            if (mask[b * Ss + col + 1]) mb1 |= (1u << bit);
        }

    {
        int row = tid >> 2;
        int c0 = (tid & 3) << 1;
        const size_t base = ((size_t)(b * Ss + q0 + row)) * Dd + h * HD;
#pragma unroll
        for (int i = 0; i < 2; i++) {
            int c = c0 + i;
            int swc = (c ^ (row & 7)) << 3;
            *(uint4*)&Qh[row][swc] = *(const uint4*)(qh + base + (c << 3));
            *(uint4*)&Ql[row][swc] = *(const uint4*)(ql + base + (c << 3));
        }
    }

    float rs[2][2] = {{0.f, 0.f}, {0.f, 0.f}};
    const float sc = 0.125f;
    const size_t fb = ((size_t)(bh * 16 + qt)) * 16 * 2048 + (size_t)warp * 256 + (lane << 2);

    for (int kt = 0; kt < 16; kt++) {
        const int k0 = kt << 6;
        __syncthreads();
        {
            int row = tid >> 2;
            int c0 = (tid & 3) << 1;
            const size_t base = ((size_t)(b * Ss + k0 + row)) * Dd + h * HD;
#pragma unroll
            for (int i = 0; i < 2; i++) {
                int c = c0 + i;
                int swc = (c ^ (row & 7)) << 3;
                *(uint4*)&Kh[row][swc] = *(const uint4*)(kh + base + (c << 3));
                *(uint4*)&Kl[row][swc] = *(const uint4*)(kl + base + (c << 3));
            }
        }
        __syncthreads();

        float eacc[2][2][4];
#pragma unroll
        for (int i = 0; i < 2; i++)
#pragma unroll
            for (int j = 0; j < 2; j++)
#pragma unroll
                for (int r = 0; r < 4; r++) eacc[i][j][r] = 0.f;

#pragma unroll
        for (int ks = 0; ks < 4; ks++) {
            const int r15 = lane & 15;
            const int choff = (ks << 1) + (lane >> 4);
            uint32_t aH[2][4], aL[2][4];
#pragma unroll
            for (int mf = 0; mf < 2; mf++) {
                int row = wm + (mf << 4) + r15;
                int off = row * 128 + ((choff ^ (row & 7)) << 4);
                ldsm_x4(aH[mf], qh0 + off);
                ldsm_x4(aL[mf], ql0 + off);
            }
            int nrow = wn + ((lane >> 4) << 3) + (lane & 7);
            int kch = (ks << 1) + ((lane >> 3) & 1);
            int boff = nrow * 128 + ((kch ^ (nrow & 7)) << 4);
            uint32_t bH[4], bL[4];
            ldsm_x4(bH, kh0 + boff);
            ldsm_x4(bL, kl0 + boff);
#pragma unroll
            for (int mf = 0; mf < 2; mf++)
#pragma unroll
                for (int nf = 0; nf < 2; nf++) {
                    mma16816(eacc[mf][nf], aH[mf], bH + nf * 2);
                    mma16816(eacc[mf][nf], aH[mf], bL + nf * 2);
                    mma16816(eacc[mf][nf], aL[mf], bH + nf * 2);
                }
        }

#pragma unroll
        for (int mf = 0; mf < 2; mf++) {
            float e[2][4];
#pragma unroll
            for (int nf = 0; nf < 2; nf++) {
                int bit = (kt << 1) | nf;
                int m0 = (mb0 >> bit) & 1;
                int m1 = (mb1 >> bit) & 1;
                e[nf][0] = m0 ? __expf(eacc[mf][nf][0] * sc) : 0.f;
                e[nf][1] = m1 ? __expf(eacc[mf][nf][1] * sc) : 0.f;
                e[nf][2] = m0 ? __expf(eacc[mf][nf][2] * sc) : 0.f;
                e[nf][3] = m1 ? __expf(eacc[mf][nf][3] * sc) : 0.f;
                rs[mf][0] += e[nf][0] + e[nf][1];
                rs[mf][1] += e[nf][2] + e[nf][3];
            }
            uint4 H, L;
            split2(e[0][0], e[0][1], H.x, L.x);
            split2(e[0][2], e[0][3], H.y, L.y);
            split2(e[1][0], e[1][1], H.z, L.z);
            split2(e[1][2], e[1][3], H.w, L.w);
            size_t off = fb + (size_t)kt * 2048 + (mf << 7);
            *(uint4*)(Pfh + off) = H;
            *(uint4*)(Pfl + off) = L;
        }
    }

#pragma unroll
    for (int mf = 0; mf < 2; mf++)
#pragma unroll
        for (int hf = 0; hf < 2; hf++) {
            float v = rs[mf][hf];
            v += __shfl_xor_sync(0xffffffff, v, 1);
            v += __shfl_xor_sync(0xffffffff, v, 2);
            if ((lane & 3) == 0)
                red[wm + (mf << 4) + gr + (hf << 3)][warp & 3] = v;
        }
    __syncthreads();
    if (tid < 64) {
        float s = red[tid][0] + red[tid][1] + red[tid][2] + red[tid][3];
        g_rowsum[(size_t)bh * Ss + q0 + tid] = s;
    }
}

// ---- PV: hoisted P-fragment loads -> MMA; writes normalized fp32 P ----
__global__ __launch_bounds__(256) void attn_pv_tc(
    const uint32_t* __restrict__ Pfh, const uint32_t* __restrict__ Pfl,
    const __nv_bfloat16* __restrict__ vh, const __nv_bfloat16* __restrict__ vl,
    float* __restrict__ P, float* __restrict__ X)
{
    __shared__ __align__(16) __nv_bfloat16 Vh[64][64], Vl[64][64];
    __shared__ float sinv[64];

    const int tid = threadIdx.x;
    const int warp = tid >> 5, lane = tid & 31;
    const int wm = (warp >> 2) << 5;
    const int wn = (warp & 3) << 4;
    const int cw = warp & 3;
    const int bh = blockIdx.y;
    const int b = bh >> 4, h = bh & 15;
    const int qt = blockIdx.x;
    const int q0 = qt << 6;

    const uint32_t vh0 = smem_u32(&Vh[0][0]);
    const uint32_t vl0 = smem_u32(&Vl[0][0]);
    const int gr = lane >> 2, gc = (lane & 3) << 1;
    const int r15 = lane & 15;

    if (tid < 64)
        sinv[tid] = 1.0f / g_rowsum[(size_t)bh * Ss + q0 + tid];
    __syncthreads();

    float iv[2][2];
#pragma unroll
    for (int mf = 0; mf < 2; mf++) {
        iv[mf][0] = sinv[wm + (mf << 4) + gr];
        iv[mf][1] = sinv[wm + (mf << 4) + gr + 8];
    }

    float xacc[2][2][4];
#pragma unroll
    for (int i = 0; i < 2; i++)
#pragma unroll
        for (int j = 0; j < 2; j++)
#pragma unroll
            for (int r = 0; r < 4; r++) xacc[i][j][r] = 0.f;

    const size_t fb = ((size_t)(bh * 16 + qt)) * 16 * 2048 +
                      (size_t)((warp >> 2) << 2) * 256 + (lane << 2);

    for (int kt = 0; kt < 16; kt++) {
        const int k0 = kt << 6;
        const size_t fkt = fb + (size_t)kt * 2048;

        // hoisted: ALL P fragments for this k-tile (LDG latency overlaps V fill + syncs)
        uint4 H[4][2], L[4][2];
#pragma unroll
        for (int c = 0; c < 4; c++)
#pragma unroll
            for (int mf = 0; mf < 2; mf++) {
                size_t off = fkt + (size_t)c * 256 + (mf << 7);
                H[c][mf] = *(const uint4*)(Pfh + off);
                L[c][mf] = *(const uint4*)(Pfl + off);
            }

        __syncthreads();
        {
            int row = tid >> 2;
            int c0 = (tid & 3) << 1;
            const size_t base = ((size_t)(b * Ss + k0 + row)) * Dd + h * HD;
#pragma unroll
            for (int i = 0; i < 2; i++) {
                int c = c0 + i;
                int swc = (c ^ (row & 7)) << 3;
                *(uint4*)&Vh[row][swc] = *(const uint4*)(vh + base + (c << 3));
                *(uint4*)&Vl[row][swc] = *(const uint4*)(vl + base + (c << 3));
            }
        }
        __syncthreads();

        // normalized fp32 P write for this warp's chunk cw
#pragma unroll
        for (int mf = 0; mf < 2; mf++) {
            int row0 = q0 + wm + (mf << 4) + gr;
            int col0 = k0 + (cw << 4) + gc;
            float2 hx, lx;
            hx = bf2f2(H[cw][mf].x); lx = bf2f2(L[cw][mf].x);
            *(float2*)(P + ((size_t)bh * Ss + row0) * Ss + col0) =
                make_float2((hx.x + lx.x) * iv[mf][0], (hx.y + lx.y) * iv[mf][0]);
            hx = bf2f2(H[cw][mf].y); lx = bf2f2(L[cw][mf].y);
            *(float2*)(P + ((size_t)bh * Ss + row0 + 8) * Ss + col0) =
                make_float2((hx.x + lx.x) * iv[mf][1], (hx.y + lx.y) * iv[mf][1]);
            hx = bf2f2(H[cw][mf].z); lx = bf2f2(L[cw][mf].z);
            *(float2*)(P + ((size_t)bh * Ss + row0) * Ss + col0 + 8) =
                make_float2((hx.x + lx.x) * iv[mf][0], (hx.y + lx.y) * iv[mf][0]);
            hx = bf2f2(H[cw][mf].w); lx = bf2f2(L[cw][mf].w);
            *(float2*)(P + ((size_t)bh * Ss + row0 + 8) * Ss + col0 + 8) =
                make_float2((hx.x + lx.x) * iv[mf][1], (hx.y + lx.y) * iv[mf][1]);
        }

        // MMA over the 4 k16 chunks (A frags already in registers)
#pragma unroll
        for (int c = 0; c < 4; c++) {
            const int krow = (c << 4) + r15;
            const int swk = krow & 7;
            uint32_t bH[2][2], bL[2][2];
#pragma unroll
            for (int nf = 0; nf < 2; nf++) {
                int chunk = (wn + (nf << 3)) >> 3;
                int boff = krow * 128 + ((chunk ^ swk) << 4);
                ldsm_x2t(bH[nf], vh0 + boff);
                ldsm_x2t(bL[nf], vl0 + boff);
            }
#pragma unroll
            for (int mf = 0; mf < 2; mf++)
#pragma unroll
                for (int nf = 0; nf < 2; nf++) {
                    mma16816(xacc[mf][nf], (uint32_t*)&H[c][mf], bH[nf]);
                    mma16816(xacc[mf][nf], (uint32_t*)&H[c][mf], bL[nf]);
                    mma16816(xacc[mf][nf], (uint32_t*)&L[c][mf], bH[nf]);
                }
        }
    }

#pragma unroll
    for (int mf = 0; mf < 2; mf++) {
        int row0 = q0 + wm + (mf << 4) + gr;
#pragma unroll
        for (int nf = 0; nf < 2; nf++) {
            int col = h * HD + wn + (nf << 3) + gc;
            *(float2*)(X + ((size_t)(b * Ss + row0)) * Dd + col) =
                make_float2(xacc[mf][nf][0] * iv[mf][0], xacc[mf][nf][1] * iv[mf][0]);
            *(float2*)(X + ((size_t)(b * Ss + row0 + 8)) * Dd + col) =
                make_float2(xacc[mf][nf][2] * iv[mf][1], xacc[mf][nf][3] * iv[mf][1]);
        }
    }
}

// ---------------- launch ----------------
extern "C" void kernel_launch(void* const* d_in, const int* in_sizes, int n_in,
                              void* d_out, int out_size)
{
    const float* query = (const float*)d_in[0];
    const float* key   = (const float*)d_in[1];
    const float* value = (const float*)d_in[2];
    const int*   mask  = (const int*)d_in[3];
    const float* Wq = (const float*)d_in[4];  const float* bq = (const float*)d_in[5];
    const float* Wk = (const float*)d_in[6];  const float* bk = (const float*)d_in[7];
    const float* Wv = (const float*)d_in[8];  const float* bv = (const float*)d_in[9];
    const float* Wo = (const float*)d_in[10]; const float* bo = (const float*)d_in[11];

    float* out = (float*)d_out;
    const size_t BSD = (size_t)Bb * Ss * Dd;
    const size_t ATT = (size_t)BHt * Ss * Ss;

    void *pqh, *pql, *pkh, *pkl, *pvh, *pvl, *px, *ppfh, *ppfl;
    void *pwqh, *pwql, *pwkh, *pwkl, *pwvh, *pwvl, *pwoh, *pwol;
    cudaGetSymbolAddress(&pqh, g_qh);
    cudaGetSymbolAddress(&pql, g_ql);
    cudaGetSymbolAddress(&pkh, g_kh);
    cudaGetSymbolAddress(&pkl, g_kl);
    cudaGetSymbolAddress(&pvh, g_vh);
    cudaGetSymbolAddress(&pvl, g_vl);
    cudaGetSymbolAddress(&px, g_x);
    cudaGetSymbolAddress(&ppfh, g_pfh);
    cudaGetSymbolAddress(&ppfl, g_pfl);
    cudaGetSymbolAddress(&pwqh, g_wqh);
    cudaGetSymbolAddress(&pwql, g_wql);
    cudaGetSymbolAddress(&pwkh, g_wkh);
    cudaGetSymbolAddress(&pwkl, g_wkl);
    cudaGetSymbolAddress(&pwvh, g_wvh);
    cudaGetSymbolAddress(&pwvl, g_wvl);
    cudaGetSymbolAddress(&pwoh, g_woh);
    cudaGetSymbolAddress(&pwol, g_wol);
    __nv_bfloat16* qh = (__nv_bfloat16*)pqh;
    __nv_bfloat16* ql = (__nv_bfloat16*)pql;
    __nv_bfloat16* kh = (__nv_bfloat16*)pkh;
    __nv_bfloat16* kl = (__nv_bfloat16*)pkl;
    __nv_bfloat16* vh = (__nv_bfloat16*)pvh;
    __nv_bfloat16* vl = (__nv_bfloat16*)pvl;
    uint32_t* pfh = (uint32_t*)ppfh;
    uint32_t* pfl = (uint32_t*)ppfl;
    __nv_bfloat16* wqh = (__nv_bfloat16*)pwqh;
    __nv_bfloat16* wql = (__nv_bfloat16*)pwql;
    __nv_bfloat16* wkh = (__nv_bfloat16*)pwkh;
    __nv_bfloat16* wkl = (__nv_bfloat16*)pwkl;
    __nv_bfloat16* wvh = (__nv_bfloat16*)pwvh;
    __nv_bfloat16* wvl = (__nv_bfloat16*)pwvl;
    __nv_bfloat16* woh = (__nv_bfloat16*)pwoh;
    __nv_bfloat16* wol = (__nv_bfloat16*)pwol;
    float* x = (float*)px;

    float* P;
    if ((size_t)out_size >= BSD + ATT) {
        P = out + BSD;
    } else {
        void* pp;
        cudaGetSymbolAddress(&pp, g_p_fallback);
        P = (float*)pp;
    }

    static cudaStream_t s2 = nullptr;
    static cudaEvent_t evFork = nullptr, evK = nullptr, evV = nullptr;
    if (!s2) {
        cudaStreamCreateWithFlags(&s2, cudaStreamNonBlocking);
        cudaEventCreateWithFlags(&evFork, cudaEventDisableTiming);
        cudaEventCreateWithFlags(&evK, cudaEventDisableTiming);
        cudaEventCreateWithFlags(&evV, cudaEventDisableTiming);
    }

    dim3 gemm_grid(Dd / 128, Mrows / 128);      // (8, 32)
    const int nW8 = Dd * Dd / 8;

    // fork side stream
    cudaEventRecord(evFork, 0);
    cudaStreamWaitEvent(s2, evFork, 0);

    // s2: K projection (concurrent with Q), then V, then Wo split
    split_w<<<nW8 / 256, 256, 0, s2>>>(Wk, wkh, wkl);
    gemm_aw_tc<<<gemm_grid, 256, 0, s2>>>(key, wkh, wkl, bk, nullptr, kh, kl, 1, Mrows, Dd, Dd);
    cudaEventRecord(evK, s2);
    split_w<<<nW8 / 256, 256, 0, s2>>>(Wv, wvh, wvl);
    gemm_aw_tc<<<gemm_grid, 256, 0, s2>>>(value, wvh, wvl, bv, nullptr, vh, vl, 1, Mrows, Dd, Dd);
    split_w<<<nW8 / 256, 256, 0, s2>>>(Wo, woh, wol);
    cudaEventRecord(evV, s2);

    // main: Q projection, energy (needs K), PV (needs V), O-GEMM (needs Wo)
    split_w<<<nW8 / 256, 256>>>(Wq, wqh, wql);
    gemm_aw_tc<<<gemm_grid, 256>>>(query, wqh, wql, bq, nullptr, qh, ql, 1, Mrows, Dd, Dd);
    cudaStreamWaitEvent(0, evK, 0);
    attn_energy_tc<<<dim3(Ss / 64, BHt), 256>>>(qh, ql, kh, kl, mask, pfh, pfl);
    cudaStreamWaitEvent(0, evV, 0);
    attn_pv_tc<<<dim3(Ss / 64, BHt), 256>>>(pfh, pfl, vh, vl, P, x);

    gemm_aw_tc<<<gemm_grid, 256>>>(x, woh, wol, bo, out, nullptr, nullptr, 0, Mrows, Dd, Dd);
}

// round 17
// speedup vs baseline: 1.1414x; 1.1414x over previous
#include <cuda_runtime.h>
#include <cuda_bf16.h>
#include <math.h>
#include <stdint.h>

#define Bb 4
#define Ss 1024
#define Dd 1024
#define Hh 16
#define HD 64
#define BHt (Bb*Hh)
#define Mrows (Bb*Ss)

// ---------------- device scratch ----------------
__device__ __nv_bfloat16 g_qh[(size_t)Mrows*Dd];
__device__ __nv_bfloat16 g_ql[(size_t)Mrows*Dd];
__device__ __nv_bfloat16 g_kh[(size_t)Mrows*Dd];
__device__ __nv_bfloat16 g_kl[(size_t)Mrows*Dd];
__device__ __nv_bfloat16 g_vh[(size_t)Mrows*Dd];
__device__ __nv_bfloat16 g_vl[(size_t)Mrows*Dd];
__device__ __nv_bfloat16 g_wqh[(size_t)Dd*Dd];
__device__ __nv_bfloat16 g_wql[(size_t)Dd*Dd];
__device__ __nv_bfloat16 g_wkh[(size_t)Dd*Dd];
__device__ __nv_bfloat16 g_wkl[(size_t)Dd*Dd];
__device__ __nv_bfloat16 g_wvh[(size_t)Dd*Dd];
__device__ __nv_bfloat16 g_wvl[(size_t)Dd*Dd];
__device__ __nv_bfloat16 g_woh[(size_t)Dd*Dd];
__device__ __nv_bfloat16 g_wol[(size_t)Dd*Dd];
__device__ float g_x[(size_t)Mrows*Dd];
__device__ float g_rowsum[(size_t)BHt*Ss];
__device__ float g_p_fallback[(size_t)BHt*Ss*Ss];

// ---------------- helpers ----------------
__device__ __forceinline__ uint32_t smem_u32(const void* p) {
    uint32_t a;
    asm("{ .reg .u64 t; cvta.to.shared.u64 t, %1; cvt.u32.u64 %0, t; }" : "=r"(a) : "l"(p));
    return a;
}
__device__ __forceinline__ void ldsm_x4(uint32_t* r, uint32_t addr) {
    asm volatile("ldmatrix.sync.aligned.m8n8.x4.shared.b16 {%0,%1,%2,%3}, [%4];"
                 : "=r"(r[0]), "=r"(r[1]), "=r"(r[2]), "=r"(r[3]) : "r"(addr));
}
__device__ __forceinline__ void ldsm_x2t(uint32_t* r, uint32_t addr) {
    asm volatile("ldmatrix.sync.aligned.m8n8.x2.trans.shared.b16 {%0,%1}, [%2];"
                 : "=r"(r[0]), "=r"(r[1]) : "r"(addr));
}
__device__ __forceinline__ void mma16816(float* c, const uint32_t* a, const uint32_t* b) {
    asm volatile(
        "mma.sync.aligned.m16n8k16.row.col.f32.bf16.bf16.f32 "
        "{%0,%1,%2,%3}, {%4,%5,%6,%7}, {%8,%9}, {%0,%1,%2,%3};"
        : "+f"(c[0]), "+f"(c[1]), "+f"(c[2]), "+f"(c[3])
        : "r"(a[0]), "r"(a[1]), "r"(a[2]), "r"(a[3]), "r"(b[0]), "r"(b[1]));
}
__device__ __forceinline__ void split2(float x, float y, uint32_t& h, uint32_t& l) {
    __nv_bfloat16 hx = __float2bfloat16_rn(x);
    __nv_bfloat16 hy = __float2bfloat16_rn(y);
    __nv_bfloat162 hp; hp.x = hx; hp.y = hy;
    __nv_bfloat162 lp;
    lp.x = __float2bfloat16_rn(x - __bfloat162float(hx));
    lp.y = __float2bfloat16_rn(y - __bfloat162float(hy));
    h = *(uint32_t*)&hp;
    l = *(uint32_t*)&lp;
}
__device__ __forceinline__ void split8(const float4 a, const float4 b, uint4& h, uint4& l) {
    split2(a.x, a.y, h.x, l.x);
    split2(a.z, a.w, h.y, l.y);
    split2(b.x, b.y, h.z, l.z);
    split2(b.z, b.w, h.w, l.w);
}

// ---------------- fp32 -> bf16 hi/lo split (weights, one-time) ----------------
__global__ __launch_bounds__(256) void split_w(
    const float* __restrict__ x, __nv_bfloat16* __restrict__ hi,
    __nv_bfloat16* __restrict__ lo)
{
    int i = blockIdx.x * blockDim.x + threadIdx.x;
    float4 v0 = ((const float4*)x)[2 * i];
    float4 v1 = ((const float4*)x)[2 * i + 1];
    uint4 h, l;
    split8(v0, v1, h, l);
    ((uint4*)hi)[i] = h;
    ((uint4*)lo)[i] = l;
}

// --------- round-12 128x128 GEMM: A fp32 (in-kernel split), W pre-split bf16 ---------
__global__ __launch_bounds__(256, 2) void gemm_aw_tc(
    const float* __restrict__ A,
    const __nv_bfloat16* __restrict__ Bh, const __nv_bfloat16* __restrict__ Bl,
    const float* __restrict__ bias,
    float* __restrict__ Cf, __nv_bfloat16* __restrict__ Ch,
    __nv_bfloat16* __restrict__ Cl, int mode,
    int Mn, int Nn, int Kn)
{
    __shared__ __align__(16) __nv_bfloat16 As[128][64];
    __shared__ __align__(16) __nv_bfloat16 Bs[2][32][128];

    const int tid = threadIdx.x;
    const int warp = tid >> 5, lane = tid & 31;
    const int wm = (warp >> 2) << 6;
    const int wn = (warp & 3) << 5;
    const int bm = blockIdx.y << 7, bn = blockIdx.x << 7;

    const uint32_t as0 = smem_u32(&As[0][0]);
    const uint32_t bs0 = smem_u32(&Bs[0][0][0]);

    float acc[4][4][4];
#pragma unroll
    for (int i = 0; i < 4; i++)
#pragma unroll
        for (int j = 0; j < 4; j++)
#pragma unroll
            for (int r = 0; r < 4; r++) acc[i][j][r] = 0.f;

    const int arow = tid >> 1, acol = (tid & 1) << 4;
    const float* gA = A + (size_t)(bm + arow) * Kn + acol;
    const int bk = tid >> 3, bcol = (tid & 7) << 4;
    const __nv_bfloat16* gBh = Bh + (size_t)bk * Nn + bn + bcol;
    const __nv_bfloat16* gBl = Bl + (size_t)bk * Nn + bn + bcol;

    char* apB = (char*)(&As[0][0]) + arow * 128;
    char* bpB = (char*)(&Bs[0][0][0]) + bk * 256;
    const int swa = arow & 7, swb = bk & 7;
    const int ac0 = (tid & 1) << 1;
    const int bc0 = (tid & 7) << 1;

    for (int k0 = 0; k0 < Kn; k0 += 32) {
        float4 fa0 = *(const float4*)(gA + k0);
        float4 fa1 = *(const float4*)(gA + k0 + 4);
        float4 fa2 = *(const float4*)(gA + k0 + 8);
        float4 fa3 = *(const float4*)(gA + k0 + 12);
        uint4 vbh0 = *(const uint4*)(gBh + (size_t)k0 * Nn);
        uint4 vbh1 = *(const uint4*)(gBh + (size_t)k0 * Nn + 8);
        uint4 vbl0 = *(const uint4*)(gBl + (size_t)k0 * Nn);
        uint4 vbl1 = *(const uint4*)(gBl + (size_t)k0 * Nn + 8);
        uint4 ah0, al0, ah1, al1;
        split8(fa0, fa1, ah0, al0);
        split8(fa2, fa3, ah1, al1);
        __syncthreads();
        *(uint4*)(apB + (((ac0 | 0) ^ swa) << 4)) = ah0;
        *(uint4*)(apB + (((ac0 | 1) ^ swa) << 4)) = ah1;
        *(uint4*)(apB + ((((ac0 | 0) + 4) ^ swa) << 4)) = al0;
        *(uint4*)(apB + ((((ac0 | 1) + 4) ^ swa) << 4)) = al1;
        *(uint4*)(bpB + (((bc0 | 0) ^ swb) << 4)) = vbh0;
        *(uint4*)(bpB + (((bc0 | 1) ^ swb) << 4)) = vbh1;
        *(uint4*)(bpB + 8192 + (((bc0 | 0) ^ swb) << 4)) = vbl0;
        *(uint4*)(bpB + 8192 + (((bc0 | 1) ^ swb) << 4)) = vbl1;
        __syncthreads();

#pragma unroll
        for (int ks = 0; ks < 2; ks++) {
            const int r15 = lane & 15;
            const int choff = (ks << 1) + (lane >> 4);
            uint32_t bf[2][4][2];
            const int krow = (ks << 4) + r15;
            const int swk = krow & 7;
#pragma unroll
            for (int nf = 0; nf < 4; nf++) {
                int chunk = (wn + (nf << 3)) >> 3;
                uint32_t ad = bs0 + krow * 256 + ((chunk ^ swk) << 4);
                ldsm_x2t(bf[0][nf], ad);
                ldsm_x2t(bf[1][nf], ad + 8192);
            }
            uint32_t af[4][4];
#pragma unroll
            for (int mf = 0; mf < 4; mf++) {
                int row = wm + (mf << 4) + r15;
                int sw = row & 7;
                ldsm_x4(af[mf], as0 + row * 128 + ((choff ^ sw) << 4));
            }
#pragma unroll
            for (int mf = 0; mf < 4; mf++)
#pragma unroll
                for (int nf = 0; nf < 4; nf++) {
                    mma16816(acc[mf][nf], af[mf], bf[0][nf]);
                    mma16816(acc[mf][nf], af[mf], bf[1][nf]);
                }
#pragma unroll
            for (int mf = 0; mf < 4; mf++) {
                int row = wm + (mf << 4) + r15;
                int sw = row & 7;
                ldsm_x4(af[mf], as0 + row * 128 + (((choff + 4) ^ sw) << 4));
            }
#pragma unroll
            for (int mf = 0; mf < 4; mf++)
#pragma unroll
                for (int nf = 0; nf < 4; nf++)
                    mma16816(acc[mf][nf], af[mf], bf[0][nf]);
        }
    }

    const int gr = lane >> 2, gc = (lane & 3) << 1;
#pragma unroll
    for (int mf = 0; mf < 4; mf++) {
        int r0 = bm + wm + (mf << 4) + gr;
#pragma unroll
        for (int nf = 0; nf < 4; nf++) {
            int col = bn + wn + (nf << 3) + gc;
            float2 bv = *(const float2*)(bias + col);
            float c00 = acc[mf][nf][0] + bv.x, c01 = acc[mf][nf][1] + bv.y;
            float c10 = acc[mf][nf][2] + bv.x, c11 = acc[mf][nf][3] + bv.y;
            if (mode == 0) {
                *(float2*)(Cf + (size_t)r0 * Nn + col) = make_float2(c00, c01);
                *(float2*)(Cf + (size_t)(r0 + 8) * Nn + col) = make_float2(c10, c11);
            } else {
                uint32_t h, l;
                split2(c00, c01, h, l);
                *(uint32_t*)(Ch + (size_t)r0 * Nn + col) = h;
                *(uint32_t*)(Cl + (size_t)r0 * Nn + col) = l;
                split2(c10, c11, h, l);
                *(uint32_t*)(Ch + (size_t)(r0 + 8) * Nn + col) = h;
                *(uint32_t*)(Cl + (size_t)(r0 + 8) * Nn + col) = l;
            }
        }
    }
}

// ---- energy: round-3 + register-cached mask bitmask ----
__global__ __launch_bounds__(256) void attn_energy_tc(
    const __nv_bfloat16* __restrict__ qh, const __nv_bfloat16* __restrict__ ql,
    const __nv_bfloat16* __restrict__ kh, const __nv_bfloat16* __restrict__ kl,
    const int* __restrict__ mask, float* __restrict__ P)
{
    __shared__ __align__(16) __nv_bfloat16 Qh[64][64], Ql[64][64];
    __shared__ __align__(16) __nv_bfloat16 Kh[64][64], Kl[64][64];
    __shared__ float red[64][4];

    const int tid = threadIdx.x;
    const int warp = tid >> 5, lane = tid & 31;
    const int wm = (warp >> 2) << 5;
    const int wn = (warp & 3) << 4;
    const int bh = blockIdx.y;
    const int b = bh >> 4, h = bh & 15;
    const int q0 = blockIdx.x << 6;

    const uint32_t qh0 = smem_u32(&Qh[0][0]);
    const uint32_t ql0 = smem_u32(&Ql[0][0]);
    const uint32_t kh0 = smem_u32(&Kh[0][0]);
    const uint32_t kl0 = smem_u32(&Kl[0][0]);

    const int gr = lane >> 2, gc = (lane & 3) << 1;

    uint32_t mb0 = 0, mb1 = 0;
#pragma unroll
    for (int kt = 0; kt < 16; kt++)
#pragma unroll
        for (int nf = 0; nf < 2; nf++) {
            int col = (kt << 6) + wn + (nf << 3) + gc;
            int bit = (kt << 1) | nf;
            if (mask[b * Ss + col]) mb0 |= (1u << bit);
            if (mask[b * Ss + col + 1]) mb1 |= (1u << bit);
        }

    {
        int row = tid >> 2;
        int c0 = (tid & 3) << 1;
        const size_t base = ((size_t)(b * Ss + q0 + row)) * Dd + h * HD;
#pragma unroll
        for (int i = 0; i < 2; i++) {
            int c = c0 + i;
            int swc = (c ^ (row & 7)) << 3;
            *(uint4*)&Qh[row][swc] = *(const uint4*)(qh + base + (c << 3));
            *(uint4*)&Ql[row][swc] = *(const uint4*)(ql + base + (c << 3));
        }
    }

    float rs[2][2] = {{0.f, 0.f}, {0.f, 0.f}};
    const float sc = 0.125f;

    for (int kt = 0; kt < 16; kt++) {
        const int k0 = kt << 6;
        __syncthreads();
        {
            int row = tid >> 2;
            int c0 = (tid & 3) << 1;
            const size_t base = ((size_t)(b * Ss + k0 + row)) * Dd + h * HD;
#pragma unroll
            for (int i = 0; i < 2; i++) {
                int c = c0 + i;
                int swc = (c ^ (row & 7)) << 3;
                *(uint4*)&Kh[row][swc] = *(const uint4*)(kh + base + (c << 3));
                *(uint4*)&Kl[row][swc] = *(const uint4*)(kl + base + (c << 3));
            }
        }
        __syncthreads();

        float eacc[2][2][4];
#pragma unroll
        for (int i = 0; i < 2; i++)
#pragma unroll
            for (int j = 0; j < 2; j++)
#pragma unroll
                for (int r = 0; r < 4; r++) eacc[i][j][r] = 0.f;

#pragma unroll
        for (int ks = 0; ks < 4; ks++) {
            const int r15 = lane & 15;
            const int choff = (ks << 1) + (lane >> 4);
            uint32_t aH[2][4], aL[2][4];
#pragma unroll
            for (int mf = 0; mf < 2; mf++) {
                int row = wm + (mf << 4) + r15;
                int off = row * 128 + ((choff ^ (row & 7)) << 4);
                ldsm_x4(aH[mf], qh0 + off);
                ldsm_x4(aL[mf], ql0 + off);
            }
            int nrow = wn + ((lane >> 4) << 3) + (lane & 7);
            int kch = (ks << 1) + ((lane >> 3) & 1);
            int boff = nrow * 128 + ((kch ^ (nrow & 7)) << 4);
            uint32_t bH[4], bL[4];
            ldsm_x4(bH, kh0 + boff);
            ldsm_x4(bL, kl0 + boff);
#pragma unroll
            for (int mf = 0; mf < 2; mf++)
#pragma unroll
                for (int nf = 0; nf < 2; nf++) {
                    mma16816(eacc[mf][nf], aH[mf], bH + nf * 2);
                    mma16816(eacc[mf][nf], aH[mf], bL + nf * 2);
                    mma16816(eacc[mf][nf], aL[mf], bH + nf * 2);
                }
        }

#pragma unroll
        for (int mf = 0; mf < 2; mf++) {
            int row0 = q0 + wm + (mf << 4) + gr;
#pragma unroll
            for (int nf = 0; nf < 2; nf++) {
                int col = k0 + wn + (nf << 3) + gc;
                int bit = (kt << 1) | nf;
                int m0 = (mb0 >> bit) & 1;
                int m1 = (mb1 >> bit) & 1;
                float e0 = m0 ? __expf(eacc[mf][nf][0] * sc) : 0.f;
                float e1 = m1 ? __expf(eacc[mf][nf][1] * sc) : 0.f;
                float e2 = m0 ? __expf(eacc[mf][nf][2] * sc) : 0.f;
                float e3 = m1 ? __expf(eacc[mf][nf][3] * sc) : 0.f;
                rs[mf][0] += e0 + e1;
                rs[mf][1] += e2 + e3;
                *(float2*)(P + ((size_t)bh * Ss + row0) * Ss + col) = make_float2(e0, e1);
                *(float2*)(P + ((size_t)bh * Ss + row0 + 8) * Ss + col) = make_float2(e2, e3);
            }
        }
    }

#pragma unroll
    for (int mf = 0; mf < 2; mf++)
#pragma unroll
        for (int hf = 0; hf < 2; hf++) {
            float v = rs[mf][hf];
            v += __shfl_xor_sync(0xffffffff, v, 1);
            v += __shfl_xor_sync(0xffffffff, v, 2);
            if ((lane & 3) == 0)
                red[wm + (mf << 4) + gr + (hf << 3)][warp & 3] = v;
        }
    __syncthreads();
    if (tid < 64) {
        float s = red[tid][0] + red[tid][1] + red[tid][2] + red[tid][3];
        g_rowsum[(size_t)bh * Ss + q0 + tid] = s;
    }
}

// ---- PV (round-14 + hoisted P loads): normalize + P write + X = P@V ----
__global__ __launch_bounds__(256) void attn_pv_tc(
    float* __restrict__ P,
    const __nv_bfloat16* __restrict__ vh, const __nv_bfloat16* __restrict__ vl,
    float* __restrict__ X)
{
    __shared__ __align__(16) __nv_bfloat16 Ph[64][64], Pl[64][64];
    __shared__ __align__(16) __nv_bfloat16 Vh[64][64], Vl[64][64];
    __shared__ float sinv[64];

    const int tid = threadIdx.x;
    const int warp = tid >> 5, lane = tid & 31;
    const int wm = (warp >> 2) << 5;
    const int wn = (warp & 3) << 4;
    const int bh = blockIdx.y;
    const int b = bh >> 4, h = bh & 15;
    const int q0 = blockIdx.x << 6;

    const uint32_t ph0 = smem_u32(&Ph[0][0]);
    const uint32_t pl0 = smem_u32(&Pl[0][0]);
    const uint32_t vh0 = smem_u32(&Vh[0][0]);
    const uint32_t vl0 = smem_u32(&Vl[0][0]);

    if (tid < 64)
        sinv[tid] = 1.0f / g_rowsum[(size_t)bh * Ss + q0 + tid];

    float acc[2][2][4];
#pragma unroll
    for (int i = 0; i < 2; i++)
#pragma unroll
        for (int j = 0; j < 2; j++)
#pragma unroll
            for (int r = 0; r < 4; r++) acc[i][j][r] = 0.f;

    const int prow = tid >> 2;
    const int pc0 = (tid & 3) << 4;
    const int pch0 = (tid & 3) << 1;

    for (int kt = 0; kt < 16; kt++) {
        const int k0 = kt << 6;
        // hoisted P loads: LDG latency overlaps the barrier + V fill below
        float* prow_g = P + ((size_t)bh * Ss + q0 + prow) * Ss + k0 + pc0;
        float4 p0 = *(float4*)(prow_g);
        float4 p1 = *(float4*)(prow_g + 4);
        float4 p2 = *(float4*)(prow_g + 8);
        float4 p3 = *(float4*)(prow_g + 12);

        __syncthreads();
        {
            int row = tid >> 2;
            int c0 = (tid & 3) << 1;
            const size_t base = ((size_t)(b * Ss + k0 + row)) * Dd + h * HD;
#pragma unroll
            for (int i = 0; i < 2; i++) {
                int c = c0 + i;
                int swc = (c ^ (row & 7)) << 3;
                *(uint4*)&Vh[row][swc] = *(const uint4*)(vh + base + (c << 3));
                *(uint4*)&Vl[row][swc] = *(const uint4*)(vl + base + (c << 3));
            }
        }
        {
            float inv = sinv[prow];
            p0.x *= inv; p0.y *= inv; p0.z *= inv; p0.w *= inv;
            p1.x *= inv; p1.y *= inv; p1.z *= inv; p1.w *= inv;
            p2.x *= inv; p2.y *= inv; p2.z *= inv; p2.w *= inv;
            p3.x *= inv; p3.y *= inv; p3.z *= inv; p3.w *= inv;
            *(float4*)(prow_g) = p0;
            *(float4*)(prow_g + 4) = p1;
            *(float4*)(prow_g + 8) = p2;
            *(float4*)(prow_g + 12) = p3;
            uint4 h0, l0, h1, l1;
            split8(p0, p1, h0, l0);
            split8(p2, p3, h1, l1);
            int sw0 = ((pch0 | 0) ^ (prow & 7)) << 3;
            int sw1 = ((pch0 | 1) ^ (prow & 7)) << 3;
            *(uint4*)&Ph[prow][sw0] = h0;
            *(uint4*)&Ph[prow][sw1] = h1;
            *(uint4*)&Pl[prow][sw0] = l0;
            *(uint4*)&Pl[prow][sw1] = l1;
        }
        __syncthreads();

#pragma unroll
        for (int ks = 0; ks < 4; ks++) {
            const int r15 = lane & 15;
            const int choff = (ks << 1) + (lane >> 4);
            uint32_t aH[2][4], aL[2][4];
#pragma unroll
            for (int mf = 0; mf < 2; mf++) {
                int row = wm + (mf << 4) + r15;
                int off = row * 128 + ((choff ^ (row & 7)) << 4);
                ldsm_x4(aH[mf], ph0 + off);
                ldsm_x4(aL[mf], pl0 + off);
            }
            const int krow = (ks << 4) + r15;
            const int swk = krow & 7;
            uint32_t bH[2][2], bL[2][2];
#pragma unroll
            for (int nf = 0; nf < 2; nf++) {
                int chunk = (wn + (nf << 3)) >> 3;
                int boff = krow * 128 + ((chunk ^ swk) << 4);
                ldsm_x2t(bH[nf], vh0 + boff);
                ldsm_x2t(bL[nf], vl0 + boff);
            }
#pragma unroll
            for (int mf = 0; mf < 2; mf++)
#pragma unroll
                for (int nf = 0; nf < 2; nf++) {
                    mma16816(acc[mf][nf], aH[mf], bH[nf]);
                    mma16816(acc[mf][nf], aH[mf], bL[nf]);
                    mma16816(acc[mf][nf], aL[mf], bH[nf]);
                }
        }
    }
    const int gr = lane >> 2, gc = (lane & 3) << 1;
#pragma unroll
    for (int mf = 0; mf < 2; mf++) {
        int row0 = q0 + wm + (mf << 4) + gr;
#pragma unroll
        for (int nf = 0; nf < 2; nf++) {
            int col = h * HD + wn + (nf << 3) + gc;
            *(float2*)(X + ((size_t)(b * Ss + row0)) * Dd + col) =
                make_float2(acc[mf][nf][0], acc[mf][nf][1]);
            *(float2*)(X + ((size_t)(b * Ss + row0 + 8)) * Dd + col) =
                make_float2(acc[mf][nf][2], acc[mf][nf][3]);
        }
    }
}

// ---------------- launch ----------------
extern "C" void kernel_launch(void* const* d_in, const int* in_sizes, int n_in,
                              void* d_out, int out_size)
{
    const float* query = (const float*)d_in[0];
    const float* key   = (const float*)d_in[1];
    const float* value = (const float*)d_in[2];
    const int*   mask  = (const int*)d_in[3];
    const float* Wq = (const float*)d_in[4];  const float* bq = (const float*)d_in[5];
    const float* Wk = (const float*)d_in[6];  const float* bk = (const float*)d_in[7];
    const float* Wv = (const float*)d_in[8];  const float* bv = (const float*)d_in[9];
    const float* Wo = (const float*)d_in[10]; const float* bo = (const float*)d_in[11];

    float* out = (float*)d_out;
    const size_t BSD = (size_t)Bb * Ss * Dd;
    const size_t ATT = (size_t)BHt * Ss * Ss;

    void *pqh, *pql, *pkh, *pkl, *pvh, *pvl, *px;
    void *pwqh, *pwql, *pwkh, *pwkl, *pwvh, *pwvl, *pwoh, *pwol;
    cudaGetSymbolAddress(&pqh, g_qh);
    cudaGetSymbolAddress(&pql, g_ql);
    cudaGetSymbolAddress(&pkh, g_kh);
    cudaGetSymbolAddress(&pkl, g_kl);
    cudaGetSymbolAddress(&pvh, g_vh);
    cudaGetSymbolAddress(&pvl, g_vl);
    cudaGetSymbolAddress(&px, g_x);
    cudaGetSymbolAddress(&pwqh, g_wqh);
    cudaGetSymbolAddress(&pwql, g_wql);
    cudaGetSymbolAddress(&pwkh, g_wkh);
    cudaGetSymbolAddress(&pwkl, g_wkl);
    cudaGetSymbolAddress(&pwvh, g_wvh);
    cudaGetSymbolAddress(&pwvl, g_wvl);
    cudaGetSymbolAddress(&pwoh, g_woh);
    cudaGetSymbolAddress(&pwol, g_wol);
    __nv_bfloat16* qh = (__nv_bfloat16*)pqh;
    __nv_bfloat16* ql = (__nv_bfloat16*)pql;
    __nv_bfloat16* kh = (__nv_bfloat16*)pkh;
    __nv_bfloat16* kl = (__nv_bfloat16*)pkl;
    __nv_bfloat16* vh = (__nv_bfloat16*)pvh;
    __nv_bfloat16* vl = (__nv_bfloat16*)pvl;
    __nv_bfloat16* wqh = (__nv_bfloat16*)pwqh;
    __nv_bfloat16* wql = (__nv_bfloat16*)pwql;
    __nv_bfloat16* wkh = (__nv_bfloat16*)pwkh;
    __nv_bfloat16* wkl = (__nv_bfloat16*)pwkl;
    __nv_bfloat16* wvh = (__nv_bfloat16*)pwvh;
    __nv_bfloat16* wvl = (__nv_bfloat16*)pwvl;
    __nv_bfloat16* woh = (__nv_bfloat16*)pwoh;
    __nv_bfloat16* wol = (__nv_bfloat16*)pwol;
    float* x = (float*)px;

    float* P;
    if ((size_t)out_size >= BSD + ATT) {
        P = out + BSD;
    } else {
        void* pp;
        cudaGetSymbolAddress(&pp, g_p_fallback);
        P = (float*)pp;
    }

    static cudaStream_t s2 = nullptr;
    static cudaEvent_t evFork = nullptr, evK = nullptr, evV = nullptr;
    if (!s2) {
        cudaStreamCreateWithFlags(&s2, cudaStreamNonBlocking);
        cudaEventCreateWithFlags(&evFork, cudaEventDisableTiming);
        cudaEventCreateWithFlags(&evK, cudaEventDisableTiming);
        cudaEventCreateWithFlags(&evV, cudaEventDisableTiming);
    }

    dim3 gemm_grid(Dd / 128, Mrows / 128);      // (8, 32)
    const int nW8 = Dd * Dd / 8;

    // fork side stream
    cudaEventRecord(evFork, 0);
    cudaStreamWaitEvent(s2, evFork, 0);

    // s2: K projection (concurrent with Q), then V, then Wo split
    split_w<<<nW8 / 256, 256, 0, s2>>>(Wk, wkh, wkl);
    gemm_aw_tc<<<gemm_grid, 256, 0, s2>>>(key, wkh, wkl, bk, nullptr, kh, kl, 1, Mrows, Dd, Dd);
    cudaEventRecord(evK, s2);
    split_w<<<nW8 / 256, 256, 0, s2>>>(Wv, wvh, wvl);
    gemm_aw_tc<<<gemm_grid, 256, 0, s2>>>(value, wvh, wvl, bv, nullptr, vh, vl, 1, Mrows, Dd, Dd);
    split_w<<<nW8 / 256, 256, 0, s2>>>(Wo, woh, wol);
    cudaEventRecord(evV, s2);

    // main: Q projection, energy (needs K), PV (needs V), O-GEMM (needs Wo)
    split_w<<<nW8 / 256, 256>>>(Wq, wqh, wql);
    gemm_aw_tc<<<gemm_grid, 256>>>(query, wqh, wql, bq, nullptr, qh, ql, 1, Mrows, Dd, Dd);
    cudaStreamWaitEvent(0, evK, 0);
    attn_energy_tc<<<dim3(Ss / 64, BHt), 256>>>(qh, ql, kh, kl, mask, P);
    cudaStreamWaitEvent(0, evV, 0);
    attn_pv_tc<<<dim3(Ss / 64, BHt), 256>>>(P, vh, vl, x);

    gemm_aw_tc<<<gemm_grid, 256>>>(x, woh, wol, bo, out, nullptr, nullptr, 0, Mrows, Dd, Dd);
}